// round 1
// baseline (speedup 1.0000x reference)
#include <cuda_runtime.h>
#include <cstdint>
#include <math.h>

// Problem constants
#define BATCH   512
#define NTOK    64
#define C_DIM   768
#define K2DIM   2304          // 3*C
#define TOKENS  (BATCH * NTOK)   // 32768

// ---------------- device scratch (no allocation allowed) ----------------
__device__ float g_xfuse[(size_t)TOKENS * K2DIM];   // [token][3C], tf32-pre-rounded
__device__ float g_y[(size_t)TOKENS * C_DIM];       // stage-2 output, tf32-pre-rounded
__device__ float g_fc2p[C_DIM * K2DIM];             // fc2 * ln2_w, tf32-rounded
__device__ float g_projp[C_DIM * C_DIM];            // proj_w, tf32-rounded
__device__ float g_colsum[C_DIM];                   // sum_k ln2_w[k]*fc2[o,k]
__device__ float g_bsum[C_DIM];                     // sum_k ln2_b[k]*fc2[o,k]

// ---------------- helpers ----------------
__device__ __forceinline__ float tf32r(float x) {
    uint32_t u;
    asm("cvt.rna.tf32.f32 %0, %1;" : "=r"(u) : "f"(x));
    return __uint_as_float(u);
}

__device__ __forceinline__ float gelu_t(float x) {
    float u = 0.7978845608028654f * (x + 0.044715f * x * x * x);
    return 0.5f * x * (1.0f + tanhf(u));
}

// ---------------- K0: weight prep ----------------
__global__ void prep_fc2(const float* __restrict__ fc2, const float* __restrict__ w) {
    int i = blockIdx.x * blockDim.x + threadIdx.x;
    if (i < C_DIM * K2DIM) g_fc2p[i] = tf32r(fc2[i] * w[i % K2DIM]);
}

__global__ void prep_proj(const float* __restrict__ p) {
    int i = blockIdx.x * blockDim.x + threadIdx.x;
    if (i < C_DIM * C_DIM) g_projp[i] = tf32r(p[i]);
}

__global__ void prep_sums(const float* __restrict__ fc2, const float* __restrict__ w,
                          const float* __restrict__ b) {
    int o = blockIdx.x;
    float cs = 0.f, bs = 0.f;
    for (int k = threadIdx.x; k < K2DIM; k += blockDim.x) {
        float f = fc2[o * K2DIM + k];
        cs += f * w[k];
        bs += f * b[k];
    }
    __shared__ float scs[32], sbs[32];
    #pragma unroll
    for (int off = 16; off; off >>= 1) {
        cs += __shfl_down_sync(0xffffffffu, cs, off);
        bs += __shfl_down_sync(0xffffffffu, bs, off);
    }
    int wid = threadIdx.x >> 5, lane = threadIdx.x & 31;
    if (lane == 0) { scs[wid] = cs; sbs[wid] = bs; }
    __syncthreads();
    if (threadIdx.x == 0) {
        float c2 = 0.f, b2 = 0.f;
        int nw = blockDim.x >> 5;
        for (int i = 0; i < nw; i++) { c2 += scs[i]; b2 += sbs[i]; }
        g_colsum[o] = c2; g_bsum[o] = b2;
    }
}

// ---------------- K1: per-(b,c) 8x8 mixing, builds x_fuse ----------------
// x5[b,c,i,j] = x[b, i*8+j, c]. Per channel c:
//  A = gelu(fc1 @ LNcol(M))   (LN over i, weight indexed by i)
//  W = gelu(LNrow(M) @ fc1^T) (LN over j, weight indexed by j)
//  xh = M @ A ; xw = W @ M
__global__ __launch_bounds__(256) void stage1(
        const float* __restrict__ x,
        const float* __restrict__ ln1w, const float* __restrict__ ln1b,
        const float* __restrict__ fc1w) {
    __shared__ float s_fc1[64], s_w[8], s_b[8];
    int tid = threadIdx.x;
    if (tid < 64) s_fc1[tid] = fc1w[tid];
    if (tid < 8) { s_w[tid] = ln1w[tid]; s_b[tid] = ln1b[tid]; }
    __syncthreads();

    int b = blockIdx.x;
    const float* xb = x + (size_t)b * NTOK * C_DIM;

    for (int c = tid; c < C_DIM; c += 256) {
        float M[64];
        #pragma unroll
        for (int n = 0; n < 64; n++) M[n] = xb[n * C_DIM + c];

        // ---- column LN -> A ----
        float A[64];
        #pragma unroll
        for (int j = 0; j < 8; j++) {
            float m = 0.f;
            #pragma unroll
            for (int t = 0; t < 8; t++) m += M[t * 8 + j];
            m *= 0.125f;
            float v = 0.f;
            #pragma unroll
            for (int t = 0; t < 8; t++) { float d = M[t * 8 + j] - m; v += d * d; }
            float rs = rsqrtf(v * 0.125f + 1e-5f);
            float ln[8];
            #pragma unroll
            for (int t = 0; t < 8; t++)
                ln[t] = (M[t * 8 + j] - m) * rs * s_w[t] + s_b[t];
            #pragma unroll
            for (int io = 0; io < 8; io++) {
                float acc = 0.f;
                #pragma unroll
                for (int t = 0; t < 8; t++) acc += s_fc1[io * 8 + t] * ln[t];
                A[io * 8 + j] = gelu_t(acc);
            }
        }
        // xh = M @ A ; also write x5 part
        #pragma unroll
        for (int i = 0; i < 8; i++) {
            #pragma unroll
            for (int j = 0; j < 8; j++) {
                float xh = 0.f;
                #pragma unroll
                for (int t = 0; t < 8; t++) xh += M[i * 8 + t] * A[t * 8 + j];
                float* row = g_xfuse + (size_t)(b * 64 + i * 8 + j) * K2DIM;
                row[c]         = tf32r(M[i * 8 + j]);
                row[C_DIM + c] = tf32r(xh);
            }
        }
        // ---- row LN -> W ----
        float W[64];
        #pragma unroll
        for (int i = 0; i < 8; i++) {
            float m = 0.f;
            #pragma unroll
            for (int t = 0; t < 8; t++) m += M[i * 8 + t];
            m *= 0.125f;
            float v = 0.f;
            #pragma unroll
            for (int t = 0; t < 8; t++) { float d = M[i * 8 + t] - m; v += d * d; }
            float rs = rsqrtf(v * 0.125f + 1e-5f);
            float ln[8];
            #pragma unroll
            for (int t = 0; t < 8; t++)
                ln[t] = (M[i * 8 + t] - m) * rs * s_w[t] + s_b[t];
            #pragma unroll
            for (int jo = 0; jo < 8; jo++) {
                float acc = 0.f;
                #pragma unroll
                for (int t = 0; t < 8; t++) acc += ln[t] * s_fc1[jo * 8 + t];
                W[i * 8 + jo] = gelu_t(acc);
            }
        }
        // xw = W @ M
        #pragma unroll
        for (int i = 0; i < 8; i++) {
            #pragma unroll
            for (int j = 0; j < 8; j++) {
                float xw = 0.f;
                #pragma unroll
                for (int t = 0; t < 8; t++) xw += W[i * 8 + t] * M[t * 8 + j];
                float* row = g_xfuse + (size_t)(b * 64 + i * 8 + j) * K2DIM;
                row[2 * C_DIM + c] = tf32r(xw);
            }
        }
    }
}

// ---------------- K2/K3: TF32 tensor-core GEMM ----------------
// C[M,768] = A[M,KDIM] @ B[768,KDIM]^T   (B row-major, k-contiguous)
// FUSE=true : A = g_xfuse, B = g_fc2p, epilogue = LN-fold + gelu, writes g_y
// FUSE=false: A = g_y,     B = g_projp, epilogue = +bias,         writes Cout
#define BM 128
#define BN 128
#define BK 16
#define LDT (BK + 4)   // padded smem stride (20 floats)

__device__ __forceinline__ void cp16(float* smem, const float* g) {
    uint32_t s = (uint32_t)__cvta_generic_to_shared(smem);
    asm volatile("cp.async.cg.shared.global [%0], [%1], 16;\n" :: "r"(s), "l"(g));
}

template<int KDIM, bool FUSE>
__global__ __launch_bounds__(256) void gemm_tf32(const float* __restrict__ bias,
                                                 float* __restrict__ Cout) {
    __shared__ float sA[2][BM][LDT];
    __shared__ float sB[2][BN][LDT];
    __shared__ float s_m[BM], s_r[BM], s_c0[BN], s_c1[BN];

    const float* Ag = FUSE ? g_xfuse : g_y;
    const float* Bg = FUSE ? g_fc2p : g_projp;
    float* Cp       = FUSE ? g_y    : Cout;

    int tid = threadIdx.x;
    int rowA0 = blockIdx.x * BM;
    int colB0 = blockIdx.y * BN;
    const float* Abase = Ag + (size_t)rowA0 * KDIM;
    const float* Bbase = Bg + (size_t)colB0 * KDIM;

    int lr = tid >> 2;            // 0..63
    int lc = (tid & 3) * 4;       // 0,4,8,12

    // prefetch tile 0
    {
        const float* a0 = Abase + (size_t)lr * KDIM + lc;
        cp16(&sA[0][lr][lc],      a0);
        cp16(&sA[0][lr + 64][lc], a0 + (size_t)64 * KDIM);
        const float* b0 = Bbase + (size_t)lr * KDIM + lc;
        cp16(&sB[0][lr][lc],      b0);
        cp16(&sB[0][lr + 64][lc], b0 + (size_t)64 * KDIM);
    }
    asm volatile("cp.async.commit_group;\n");

    int wid = tid >> 5, lane = tid & 31;
    int g = lane >> 2, t = lane & 3;
    int wm = (wid & 1) * 64;      // warp row base
    int wn = (wid >> 1) * 32;     // warp col base

    float acc[4][4][4];
    #pragma unroll
    for (int a = 0; a < 4; a++)
        #pragma unroll
        for (int b2 = 0; b2 < 4; b2++)
            #pragma unroll
            for (int c2 = 0; c2 < 4; c2++) acc[a][b2][c2] = 0.f;

    float rsum = 0.f, rsq = 0.f;
    int srow = tid & 127, skh = (tid >> 7) * 8;

    const int KT = KDIM / BK;
    for (int kt = 0; kt < KT; kt++) {
        int cur = kt & 1;
        if (kt + 1 < KT) {
            int nxt = cur ^ 1;
            const float* a0 = Abase + (size_t)lr * KDIM + (kt + 1) * BK + lc;
            cp16(&sA[nxt][lr][lc],      a0);
            cp16(&sA[nxt][lr + 64][lc], a0 + (size_t)64 * KDIM);
            const float* b0 = Bbase + (size_t)lr * KDIM + (kt + 1) * BK + lc;
            cp16(&sB[nxt][lr][lc],      b0);
            cp16(&sB[nxt][lr + 64][lc], b0 + (size_t)64 * KDIM);
        }
        asm volatile("cp.async.commit_group;\n");
        asm volatile("cp.async.wait_group 1;\n");
        __syncthreads();

        if (FUSE) {   // per-token LN stats from the loaded A tile
            #pragma unroll
            for (int q = 0; q < 8; q++) {
                float v = sA[cur][srow][skh + q];
                rsum += v; rsq += v * v;
            }
        }

        #pragma unroll
        for (int kk = 0; kk < BK; kk += 8) {
            uint32_t af[4][4], bf[4][2];
            #pragma unroll
            for (int mm = 0; mm < 4; mm++) {
                int r0 = wm + mm * 16 + g;
                af[mm][0] = __float_as_uint(sA[cur][r0][kk + t]);
                af[mm][1] = __float_as_uint(sA[cur][r0 + 8][kk + t]);
                af[mm][2] = __float_as_uint(sA[cur][r0][kk + t + 4]);
                af[mm][3] = __float_as_uint(sA[cur][r0 + 8][kk + t + 4]);
            }
            #pragma unroll
            for (int nn = 0; nn < 4; nn++) {
                int cc = wn + nn * 8 + g;
                bf[nn][0] = __float_as_uint(sB[cur][cc][kk + t]);
                bf[nn][1] = __float_as_uint(sB[cur][cc][kk + t + 4]);
            }
            #pragma unroll
            for (int mm = 0; mm < 4; mm++)
                #pragma unroll
                for (int nn = 0; nn < 4; nn++)
                    asm volatile(
                        "mma.sync.aligned.m16n8k8.row.col.f32.tf32.tf32.f32 "
                        "{%0,%1,%2,%3}, {%4,%5,%6,%7}, {%8,%9}, {%0,%1,%2,%3};\n"
                        : "+f"(acc[mm][nn][0]), "+f"(acc[mm][nn][1]),
                          "+f"(acc[mm][nn][2]), "+f"(acc[mm][nn][3])
                        : "r"(af[mm][0]), "r"(af[mm][1]), "r"(af[mm][2]), "r"(af[mm][3]),
                          "r"(bf[nn][0]), "r"(bf[nn][1]));
        }
        __syncthreads();
    }

    // ---- epilogue ----
    if (FUSE) {
        if (tid < 128) { s_m[tid] = rsum; s_r[tid] = rsq; }
        __syncthreads();
        if (tid >= 128) { s_m[tid - 128] += rsum; s_r[tid - 128] += rsq; }
        __syncthreads();
        if (tid < 128) {
            float mu  = s_m[tid] * (1.0f / (float)KDIM);
            float var = s_r[tid] * (1.0f / (float)KDIM) - mu * mu;
            s_m[tid] = mu;
            s_r[tid] = rsqrtf(var + 1e-5f);
            s_c0[tid] = g_colsum[colB0 + tid];
            s_c1[tid] = g_bsum[colB0 + tid];
        }
        __syncthreads();
    } else {
        if (tid < 128) s_c1[tid] = bias[colB0 + tid];
        __syncthreads();
    }

    #pragma unroll
    for (int mm = 0; mm < 4; mm++) {
        #pragma unroll
        for (int nn = 0; nn < 4; nn++) {
            #pragma unroll
            for (int rr = 0; rr < 4; rr++) {
                int rl = wm + mm * 16 + g + ((rr >= 2) ? 8 : 0);
                int cl = wn + nn * 8 + 2 * t + (rr & 1);
                float v = acc[mm][nn][rr];
                float outv;
                if (FUSE) {
                    float pre = s_r[rl] * (v - s_m[rl] * s_c0[cl]) + s_c1[cl];
                    outv = tf32r(gelu_t(pre));
                } else {
                    outv = v + s_c1[cl];
                }
                Cp[(size_t)(rowA0 + rl) * C_DIM + colB0 + cl] = outv;
            }
        }
    }
}

// ---------------- launch ----------------
extern "C" void kernel_launch(void* const* d_in, const int* in_sizes, int n_in,
                              void* d_out, int out_size) {
    const float* x     = (const float*)d_in[0];
    const float* ln1w  = (const float*)d_in[1];
    const float* ln1b  = (const float*)d_in[2];
    const float* fc1w  = (const float*)d_in[3];
    const float* ln2w  = (const float*)d_in[4];
    const float* ln2b  = (const float*)d_in[5];
    const float* fc2w  = (const float*)d_in[6];
    const float* projw = (const float*)d_in[7];
    const float* projb = (const float*)d_in[8];
    float* out = (float*)d_out;

    prep_fc2 <<<(C_DIM * K2DIM + 255) / 256, 256>>>(fc2w, ln2w);
    prep_proj<<<(C_DIM * C_DIM + 255) / 256, 256>>>(projw);
    prep_sums<<<C_DIM, 128>>>(fc2w, ln2w, ln2b);

    stage1<<<BATCH, 256>>>(x, ln1w, ln1b, fc1w);

    gemm_tf32<K2DIM, true ><<<dim3(TOKENS / BM, C_DIM / BN), 256>>>(nullptr, nullptr);
    gemm_tf32<C_DIM, false><<<dim3(TOKENS / BM, C_DIM / BN), 256>>>(projb, out);
}

// round 3
// speedup vs baseline: 1.0766x; 1.0766x over previous
#include <cuda_runtime.h>
#include <cstdint>
#include <math.h>

// Problem constants
#define BATCH   512
#define NTOK    64
#define C_DIM   768
#define K2DIM   2304          // 3*C
#define TOKENS  (BATCH * NTOK)   // 32768

// ---------------- device scratch (no allocation allowed) ----------------
__device__ float g_xfuse[(size_t)TOKENS * K2DIM];   // [token][3C], tf32-pre-rounded
__device__ float g_y[(size_t)TOKENS * C_DIM];       // stage-2 output, tf32-pre-rounded
__device__ float g_fc2p[C_DIM * K2DIM];             // fc2 * ln2_w, tf32-rounded
__device__ float g_projp[C_DIM * C_DIM];            // proj_w, tf32-rounded
__device__ float g_colsum[C_DIM];                   // sum_k ln2_w[k]*fc2[o,k]
__device__ float g_bsum[C_DIM];                     // sum_k ln2_b[k]*fc2[o,k]

// ---------------- helpers ----------------
__device__ __forceinline__ float tf32r(float x) {
    uint32_t u;
    asm("cvt.rna.tf32.f32 %0, %1;" : "=r"(u) : "f"(x));
    return __uint_as_float(u);
}

__device__ __forceinline__ float gelu_t(float x) {
    float u = 0.7978845608028654f * (x + 0.044715f * x * x * x);
    return 0.5f * x * (1.0f + tanhf(u));
}

// ---------------- K0: weight prep ----------------
__global__ void prep_fc2(const float* __restrict__ fc2, const float* __restrict__ w) {
    int i = blockIdx.x * blockDim.x + threadIdx.x;
    if (i < C_DIM * K2DIM) g_fc2p[i] = tf32r(fc2[i] * w[i % K2DIM]);
}

__global__ void prep_proj(const float* __restrict__ p) {
    int i = blockIdx.x * blockDim.x + threadIdx.x;
    if (i < C_DIM * C_DIM) g_projp[i] = tf32r(p[i]);
}

__global__ void prep_sums(const float* __restrict__ fc2, const float* __restrict__ w,
                          const float* __restrict__ b) {
    int o = blockIdx.x;
    float cs = 0.f, bs = 0.f;
    for (int k = threadIdx.x; k < K2DIM; k += blockDim.x) {
        float f = fc2[o * K2DIM + k];
        cs += f * w[k];
        bs += f * b[k];
    }
    __shared__ float scs[32], sbs[32];
    #pragma unroll
    for (int off = 16; off; off >>= 1) {
        cs += __shfl_down_sync(0xffffffffu, cs, off);
        bs += __shfl_down_sync(0xffffffffu, bs, off);
    }
    int wid = threadIdx.x >> 5, lane = threadIdx.x & 31;
    if (lane == 0) { scs[wid] = cs; sbs[wid] = bs; }
    __syncthreads();
    if (threadIdx.x == 0) {
        float c2 = 0.f, b2 = 0.f;
        int nw = blockDim.x >> 5;
        for (int i = 0; i < nw; i++) { c2 += scs[i]; b2 += sbs[i]; }
        g_colsum[o] = c2; g_bsum[o] = b2;
    }
}

// ---------------- K1: per-(b,c) 8x8 mixing (streaming, low-reg) ----------------
__global__ __launch_bounds__(256, 2) void stage1(
        const float* __restrict__ x,
        const float* __restrict__ ln1w, const float* __restrict__ ln1b,
        const float* __restrict__ fc1w) {
    __shared__ float s_fc1[64], s_w[8], s_b[8];
    int tid = threadIdx.x;
    if (tid < 64) s_fc1[tid] = fc1w[tid];
    if (tid < 8) { s_w[tid] = ln1w[tid]; s_b[tid] = ln1b[tid]; }
    __syncthreads();

    int b = blockIdx.x;
    int c = blockIdx.y * 256 + tid;          // grid.y = 3 -> c in [0,768)
    const float* xb = x + (size_t)b * NTOK * C_DIM;
    float* rowbase = g_xfuse + (size_t)b * NTOK * K2DIM;

    float M[64];
    #pragma unroll
    for (int n = 0; n < 64; n++) M[n] = xb[n * C_DIM + c];

    // x5 part
    #pragma unroll
    for (int n = 0; n < 64; n++) rowbase[(size_t)n * K2DIM + c] = tf32r(M[n]);

    // column LN -> A column j -> xh column j (streamed)
    #pragma unroll
    for (int j = 0; j < 8; j++) {
        float m = 0.f;
        #pragma unroll
        for (int t = 0; t < 8; t++) m += M[t * 8 + j];
        m *= 0.125f;
        float v = 0.f;
        #pragma unroll
        for (int t = 0; t < 8; t++) { float d = M[t * 8 + j] - m; v += d * d; }
        float rs = rsqrtf(v * 0.125f + 1e-5f);
        float ln[8];
        #pragma unroll
        for (int t = 0; t < 8; t++)
            ln[t] = (M[t * 8 + j] - m) * rs * s_w[t] + s_b[t];
        float acol[8];
        #pragma unroll
        for (int io = 0; io < 8; io++) {
            float a = 0.f;
            #pragma unroll
            for (int t = 0; t < 8; t++) a += s_fc1[io * 8 + t] * ln[t];
            acol[io] = gelu_t(a);
        }
        #pragma unroll
        for (int i = 0; i < 8; i++) {
            float xh = 0.f;
            #pragma unroll
            for (int t = 0; t < 8; t++) xh += M[i * 8 + t] * acol[t];
            rowbase[(size_t)(i * 8 + j) * K2DIM + C_DIM + c] = tf32r(xh);
        }
    }
    // row LN -> W row i -> xw row i (streamed)
    #pragma unroll
    for (int i = 0; i < 8; i++) {
        float m = 0.f;
        #pragma unroll
        for (int t = 0; t < 8; t++) m += M[i * 8 + t];
        m *= 0.125f;
        float v = 0.f;
        #pragma unroll
        for (int t = 0; t < 8; t++) { float d = M[i * 8 + t] - m; v += d * d; }
        float rs = rsqrtf(v * 0.125f + 1e-5f);
        float ln[8];
        #pragma unroll
        for (int t = 0; t < 8; t++)
            ln[t] = (M[i * 8 + t] - m) * rs * s_w[t] + s_b[t];
        float wrow[8];
        #pragma unroll
        for (int jo = 0; jo < 8; jo++) {
            float a = 0.f;
            #pragma unroll
            for (int t = 0; t < 8; t++) a += ln[t] * s_fc1[jo * 8 + t];
            wrow[jo] = gelu_t(a);
        }
        #pragma unroll
        for (int j = 0; j < 8; j++) {
            float xw = 0.f;
            #pragma unroll
            for (int t = 0; t < 8; t++) xw += wrow[t] * M[t * 8 + j];
            rowbase[(size_t)(i * 8 + j) * K2DIM + 2 * C_DIM + c] = tf32r(xw);
        }
    }
}

// ---------------- K2/K3: TF32 tensor-core GEMM (mma.sync path) ----------------
// C[M,768] = A[M,KDIM] @ B[768,KDIM]^T   (B row-major, k-contiguous)
// FUSE=true : A = g_xfuse, B = g_fc2p, epilogue = LN-fold + gelu, writes g_y
// FUSE=false: A = g_y,     B = g_projp, epilogue = +bias,         writes Cout
#define BM 128
#define BN 128
#define BK 16
#define LDT (BK + 4)   // padded smem stride (20 floats; row stride 80B is 16B-aligned)

__device__ __forceinline__ void cp16(float* smem, const float* g) {
    uint32_t s = (uint32_t)__cvta_generic_to_shared(smem);
    asm volatile("cp.async.cg.shared.global [%0], [%1], 16;\n" :: "r"(s), "l"(g));
}

template<int KDIM, bool FUSE>
__global__ __launch_bounds__(256, 2) void gemm_tf32(const float* __restrict__ bias,
                                                    float* __restrict__ Cout) {
    __shared__ float sA[2][BM][LDT];
    __shared__ float sB[2][BN][LDT];
    __shared__ float s_m[BM], s_r[BM], s_c0[BN], s_c1[BN];

    const float* Ag = FUSE ? g_xfuse : g_y;
    const float* Bg = FUSE ? g_fc2p : g_projp;
    float* Cp       = FUSE ? g_y    : Cout;

    int tid = threadIdx.x;
    // x = N-tile (6 wide) -> a wave of CTAs shares B tiles and re-reads each
    // A tile 6x out of L2 instead of DRAM.
    int rowA0 = blockIdx.y * BM;
    int colB0 = blockIdx.x * BN;
    const float* Abase = Ag + (size_t)rowA0 * KDIM;
    const float* Bbase = Bg + (size_t)colB0 * KDIM;

    int lr = tid >> 2;            // 0..63
    int lc = (tid & 3) * 4;       // 0,4,8,12

    // prefetch tile 0
    {
        const float* a0 = Abase + (size_t)lr * KDIM + lc;
        cp16(&sA[0][lr][lc],      a0);
        cp16(&sA[0][lr + 64][lc], a0 + (size_t)64 * KDIM);
        const float* b0 = Bbase + (size_t)lr * KDIM + lc;
        cp16(&sB[0][lr][lc],      b0);
        cp16(&sB[0][lr + 64][lc], b0 + (size_t)64 * KDIM);
    }
    asm volatile("cp.async.commit_group;\n");

    int wid = tid >> 5, lane = tid & 31;
    int g = lane >> 2, t = lane & 3;
    int wm = (wid & 1) * 64;      // warp row base
    int wn = (wid >> 1) * 32;     // warp col base

    float acc[4][4][4];
    #pragma unroll
    for (int a = 0; a < 4; a++)
        #pragma unroll
        for (int b2 = 0; b2 < 4; b2++)
            #pragma unroll
            for (int c2 = 0; c2 < 4; c2++) acc[a][b2][c2] = 0.f;

    float rsum = 0.f, rsq = 0.f;
    int srow = tid & 127, skh = (tid >> 7) * 8;

    const int KT = KDIM / BK;
    for (int kt = 0; kt < KT; kt++) {
        int cur = kt & 1;
        if (kt + 1 < KT) {
            int nxt = cur ^ 1;
            const float* a0 = Abase + (size_t)lr * KDIM + (kt + 1) * BK + lc;
            cp16(&sA[nxt][lr][lc],      a0);
            cp16(&sA[nxt][lr + 64][lc], a0 + (size_t)64 * KDIM);
            const float* b0 = Bbase + (size_t)lr * KDIM + (kt + 1) * BK + lc;
            cp16(&sB[nxt][lr][lc],      b0);
            cp16(&sB[nxt][lr + 64][lc], b0 + (size_t)64 * KDIM);
        }
        asm volatile("cp.async.commit_group;\n");
        asm volatile("cp.async.wait_group 1;\n");
        __syncthreads();

        if (FUSE) {   // per-token LN stats from the loaded A tile (vectorized)
            const float* rowp = &sA[cur][srow][skh];   // 16B-aligned (80B row stride)
            float4 v0 = *reinterpret_cast<const float4*>(rowp);
            float4 v1 = *reinterpret_cast<const float4*>(rowp + 4);
            rsum += v0.x + v0.y + v0.z + v0.w + v1.x + v1.y + v1.z + v1.w;
            rsq  += v0.x * v0.x + v0.y * v0.y + v0.z * v0.z + v0.w * v0.w
                  + v1.x * v1.x + v1.y * v1.y + v1.z * v1.z + v1.w * v1.w;
        }

        #pragma unroll
        for (int kk = 0; kk < BK; kk += 8) {
            uint32_t af[4][4], bf[4][2];
            #pragma unroll
            for (int mm = 0; mm < 4; mm++) {
                int r0 = wm + mm * 16 + g;
                af[mm][0] = __float_as_uint(sA[cur][r0][kk + t]);
                af[mm][1] = __float_as_uint(sA[cur][r0 + 8][kk + t]);
                af[mm][2] = __float_as_uint(sA[cur][r0][kk + t + 4]);
                af[mm][3] = __float_as_uint(sA[cur][r0 + 8][kk + t + 4]);
            }
            #pragma unroll
            for (int nn = 0; nn < 4; nn++) {
                int cc = wn + nn * 8 + g;
                bf[nn][0] = __float_as_uint(sB[cur][cc][kk + t]);
                bf[nn][1] = __float_as_uint(sB[cur][cc][kk + t + 4]);
            }
            #pragma unroll
            for (int mm = 0; mm < 4; mm++)
                #pragma unroll
                for (int nn = 0; nn < 4; nn++)
                    asm volatile(
                        "mma.sync.aligned.m16n8k8.row.col.f32.tf32.tf32.f32 "
                        "{%0,%1,%2,%3}, {%4,%5,%6,%7}, {%8,%9}, {%0,%1,%2,%3};\n"
                        : "+f"(acc[mm][nn][0]), "+f"(acc[mm][nn][1]),
                          "+f"(acc[mm][nn][2]), "+f"(acc[mm][nn][3])
                        : "r"(af[mm][0]), "r"(af[mm][1]), "r"(af[mm][2]), "r"(af[mm][3]),
                          "r"(bf[nn][0]), "r"(bf[nn][1]));
        }
        __syncthreads();
    }

    // ---- epilogue ----
    if (FUSE) {
        if (tid < 128) { s_m[tid] = rsum; s_r[tid] = rsq; }
        __syncthreads();
        if (tid >= 128) { s_m[tid - 128] += rsum; s_r[tid - 128] += rsq; }
        __syncthreads();
        if (tid < 128) {
            float mu  = s_m[tid] * (1.0f / (float)KDIM);
            float var = s_r[tid] * (1.0f / (float)KDIM) - mu * mu;
            s_m[tid] = mu;
            s_r[tid] = rsqrtf(var + 1e-5f);
            s_c0[tid] = g_colsum[colB0 + tid];
            s_c1[tid] = g_bsum[colB0 + tid];
        }
        __syncthreads();
    } else {
        if (tid < 128) s_c1[tid] = bias[colB0 + tid];
        __syncthreads();
    }

    #pragma unroll
    for (int mm = 0; mm < 4; mm++) {
        #pragma unroll
        for (int nn = 0; nn < 4; nn++) {
            #pragma unroll
            for (int rh = 0; rh < 2; rh++) {    // rh=0 -> rr{0,1}, rh=1 -> rr{2,3}
                int rl = wm + mm * 16 + g + rh * 8;
                int cl = wn + nn * 8 + 2 * t;
                float v0 = acc[mm][nn][rh * 2 + 0];
                float v1 = acc[mm][nn][rh * 2 + 1];
                float2 o;
                if (FUSE) {
                    float p0 = s_r[rl] * (v0 - s_m[rl] * s_c0[cl])     + s_c1[cl];
                    float p1 = s_r[rl] * (v1 - s_m[rl] * s_c0[cl + 1]) + s_c1[cl + 1];
                    o.x = tf32r(gelu_t(p0));
                    o.y = tf32r(gelu_t(p1));
                } else {
                    o.x = v0 + s_c1[cl];
                    o.y = v1 + s_c1[cl + 1];
                }
                *reinterpret_cast<float2*>(
                    Cp + (size_t)(rowA0 + rl) * C_DIM + colB0 + cl) = o;
            }
        }
    }
}

// ---------------- launch ----------------
extern "C" void kernel_launch(void* const* d_in, const int* in_sizes, int n_in,
                              void* d_out, int out_size) {
    const float* x     = (const float*)d_in[0];
    const float* ln1w  = (const float*)d_in[1];
    const float* ln1b  = (const float*)d_in[2];
    const float* fc1w  = (const float*)d_in[3];
    const float* ln2w  = (const float*)d_in[4];
    const float* ln2b  = (const float*)d_in[5];
    const float* fc2w  = (const float*)d_in[6];
    const float* projw = (const float*)d_in[7];
    const float* projb = (const float*)d_in[8];
    float* out = (float*)d_out;

    prep_fc2 <<<(C_DIM * K2DIM + 255) / 256, 256>>>(fc2w, ln2w);
    prep_proj<<<(C_DIM * C_DIM + 255) / 256, 256>>>(projw);
    prep_sums<<<C_DIM, 128>>>(fc2w, ln2w, ln2b);

    stage1<<<dim3(BATCH, 3), 256>>>(x, ln1w, ln1b, fc1w);

    // x = N-tiles (6), y = M-tiles (256): wave-level A reuse in L2
    gemm_tf32<K2DIM, true ><<<dim3(C_DIM / BN, TOKENS / BM), 256>>>(nullptr, nullptr);
    gemm_tf32<C_DIM, false><<<dim3(C_DIM / BN, TOKENS / BM), 256>>>(projb, out);
}

// round 4
// speedup vs baseline: 1.7923x; 1.6647x over previous
#include <cuda_runtime.h>
#include <cuda_fp16.h>
#include <cstdint>
#include <math.h>

// Problem constants
#define BATCH   512
#define NTOK    64
#define C_DIM   768
#define K2DIM   2304          // 3*C
#define TOKENS  (BATCH * NTOK)   // 32768

// ---------------- device scratch (no allocation allowed) ----------------
__device__ __half g_xfuse[(size_t)TOKENS * K2DIM];   // [token][3C], fp16
__device__ __half g_y[(size_t)TOKENS * C_DIM];       // stage-2 output, fp16
__device__ __half g_fc2p[C_DIM * K2DIM];             // fc2 * ln2_w, fp16
__device__ __half g_projp[C_DIM * C_DIM];            // proj_w, fp16
__device__ float  g_colsum[C_DIM];                   // sum_k ln2_w[k]*fc2[o,k]
__device__ float  g_bsum[C_DIM];                     // sum_k ln2_b[k]*fc2[o,k]

// ---------------- helpers ----------------
__device__ __forceinline__ float gelu_t(float x) {
    float u = 0.7978845608028654f * (x + 0.044715f * x * x * x);
    return 0.5f * x * (1.0f + tanhf(u));
}

// ---------------- K0: weight prep ----------------
__global__ void prep_fc2(const float* __restrict__ fc2, const float* __restrict__ w) {
    int i = blockIdx.x * blockDim.x + threadIdx.x;
    if (i < C_DIM * K2DIM) g_fc2p[i] = __float2half_rn(fc2[i] * w[i % K2DIM]);
}

__global__ void prep_proj(const float* __restrict__ p) {
    int i = blockIdx.x * blockDim.x + threadIdx.x;
    if (i < C_DIM * C_DIM) g_projp[i] = __float2half_rn(p[i]);
}

__global__ void prep_sums(const float* __restrict__ fc2, const float* __restrict__ w,
                          const float* __restrict__ b) {
    int o = blockIdx.x;
    float cs = 0.f, bs = 0.f;
    for (int k = threadIdx.x; k < K2DIM; k += blockDim.x) {
        float f = fc2[o * K2DIM + k];
        cs += f * w[k];
        bs += f * b[k];
    }
    __shared__ float scs[32], sbs[32];
    #pragma unroll
    for (int off = 16; off; off >>= 1) {
        cs += __shfl_down_sync(0xffffffffu, cs, off);
        bs += __shfl_down_sync(0xffffffffu, bs, off);
    }
    int wid = threadIdx.x >> 5, lane = threadIdx.x & 31;
    if (lane == 0) { scs[wid] = cs; sbs[wid] = bs; }
    __syncthreads();
    if (threadIdx.x == 0) {
        float c2 = 0.f, b2 = 0.f;
        int nw = blockDim.x >> 5;
        for (int i = 0; i < nw; i++) { c2 += scs[i]; b2 += sbs[i]; }
        g_colsum[o] = c2; g_bsum[o] = b2;
    }
}

// ---------------- K1: per-(b,c) 8x8 mixing (streaming, low-reg) ----------------
__global__ __launch_bounds__(256, 2) void stage1(
        const float* __restrict__ x,
        const float* __restrict__ ln1w, const float* __restrict__ ln1b,
        const float* __restrict__ fc1w) {
    __shared__ float s_fc1[64], s_w[8], s_b[8];
    int tid = threadIdx.x;
    if (tid < 64) s_fc1[tid] = fc1w[tid];
    if (tid < 8) { s_w[tid] = ln1w[tid]; s_b[tid] = ln1b[tid]; }
    __syncthreads();

    int b = blockIdx.x;
    int c = blockIdx.y * 256 + tid;          // grid.y = 3 -> c in [0,768)
    const float* xb = x + (size_t)b * NTOK * C_DIM;
    __half* rowbase = g_xfuse + (size_t)b * NTOK * K2DIM;

    float M[64];
    #pragma unroll
    for (int n = 0; n < 64; n++) M[n] = xb[n * C_DIM + c];

    // x5 part
    #pragma unroll
    for (int n = 0; n < 64; n++)
        rowbase[(size_t)n * K2DIM + c] = __float2half_rn(M[n]);

    // column LN -> A column j -> xh column j (streamed)
    #pragma unroll
    for (int j = 0; j < 8; j++) {
        float m = 0.f;
        #pragma unroll
        for (int t = 0; t < 8; t++) m += M[t * 8 + j];
        m *= 0.125f;
        float v = 0.f;
        #pragma unroll
        for (int t = 0; t < 8; t++) { float d = M[t * 8 + j] - m; v += d * d; }
        float rs = rsqrtf(v * 0.125f + 1e-5f);
        float ln[8];
        #pragma unroll
        for (int t = 0; t < 8; t++)
            ln[t] = (M[t * 8 + j] - m) * rs * s_w[t] + s_b[t];
        float acol[8];
        #pragma unroll
        for (int io = 0; io < 8; io++) {
            float a = 0.f;
            #pragma unroll
            for (int t = 0; t < 8; t++) a += s_fc1[io * 8 + t] * ln[t];
            acol[io] = gelu_t(a);
        }
        #pragma unroll
        for (int i = 0; i < 8; i++) {
            float xh = 0.f;
            #pragma unroll
            for (int t = 0; t < 8; t++) xh += M[i * 8 + t] * acol[t];
            rowbase[(size_t)(i * 8 + j) * K2DIM + C_DIM + c] = __float2half_rn(xh);
        }
    }
    // row LN -> W row i -> xw row i (streamed)
    #pragma unroll
    for (int i = 0; i < 8; i++) {
        float m = 0.f;
        #pragma unroll
        for (int t = 0; t < 8; t++) m += M[i * 8 + t];
        m *= 0.125f;
        float v = 0.f;
        #pragma unroll
        for (int t = 0; t < 8; t++) { float d = M[i * 8 + t] - m; v += d * d; }
        float rs = rsqrtf(v * 0.125f + 1e-5f);
        float ln[8];
        #pragma unroll
        for (int t = 0; t < 8; t++)
            ln[t] = (M[i * 8 + t] - m) * rs * s_w[t] + s_b[t];
        float wrow[8];
        #pragma unroll
        for (int jo = 0; jo < 8; jo++) {
            float a = 0.f;
            #pragma unroll
            for (int t = 0; t < 8; t++) a += ln[t] * s_fc1[jo * 8 + t];
            wrow[jo] = gelu_t(a);
        }
        #pragma unroll
        for (int j = 0; j < 8; j++) {
            float xw = 0.f;
            #pragma unroll
            for (int t = 0; t < 8; t++) xw += wrow[t] * M[t * 8 + j];
            rowbase[(size_t)(i * 8 + j) * K2DIM + 2 * C_DIM + c] = __float2half_rn(xw);
        }
    }
}

// ---------------- K2/K3: FP16 tensor-core GEMM (m16n8k16 + ldmatrix) ----------------
// C[M,768] = A[M,KDIM] @ B[768,KDIM]^T   (A,B fp16 row-major k-contiguous, fp32 acc)
#define BM 128
#define BN 128
#define BK 32                      // halves per tile row (64B)
#define LDH 40                     // padded smem stride in halves (80B, 16B-aligned)

__device__ __forceinline__ void cp16(void* smem, const void* g) {
    uint32_t s = (uint32_t)__cvta_generic_to_shared(smem);
    asm volatile("cp.async.cg.shared.global [%0], [%1], 16;\n" :: "r"(s), "l"(g));
}

template<int KDIM, bool FUSE>
__global__ __launch_bounds__(256, 2) void gemm_fp16(const __half* __restrict__ Ag,
                                                    const __half* __restrict__ Bg,
                                                    const float* __restrict__ bias,
                                                    float* __restrict__ CoutF,
                                                    __half* __restrict__ CoutH) {
    __shared__ __half sA[2][BM][LDH];
    __shared__ __half sB[2][BN][LDH];
    __shared__ float s_m[BM], s_r[BM], s_c0[BN], s_c1[BN];

    int tid = threadIdx.x;
    int rowA0 = blockIdx.y * BM;     // M tile
    int colB0 = blockIdx.x * BN;     // N tile (x fast -> wave shares A in L2)
    const __half* Abase = Ag + (size_t)rowA0 * KDIM;
    const __half* Bbase = Bg + (size_t)colB0 * KDIM;

    int lr = tid >> 1;               // 0..127 (tile row)
    int lc = (tid & 1) * 16;         // half-offset 0 or 16

    auto load_stage = [&](int buf, int kt) {
        const __half* a0 = Abase + (size_t)lr * KDIM + kt * BK + lc;
        cp16(&sA[buf][lr][lc],     a0);
        cp16(&sA[buf][lr][lc + 8], a0 + 8);
        const __half* b0 = Bbase + (size_t)lr * KDIM + kt * BK + lc;
        cp16(&sB[buf][lr][lc],     b0);
        cp16(&sB[buf][lr][lc + 8], b0 + 8);
    };

    load_stage(0, 0);
    asm volatile("cp.async.commit_group;\n");

    int wid = tid >> 5, lane = tid & 31;
    int wm = (wid & 1) * 64;         // warp row base
    int wn = (wid >> 1) * 32;        // warp col base

    // ldmatrix per-lane row offsets (in halves, within a buffer)
    uint32_t sA_u = (uint32_t)__cvta_generic_to_shared(&sA[0][0][0]);
    uint32_t sB_u = (uint32_t)__cvta_generic_to_shared(&sB[0][0][0]);
    const uint32_t BUFA = BM * LDH * 2;    // bytes per A buffer
    const uint32_t BUFB = BN * LDH * 2;

    // A: matrices (m0-7,k0),(m8-15,k0),(m0-7,k8),(m8-15,k8)
    uint32_t offA[4];
    #pragma unroll
    for (int mm = 0; mm < 4; mm++) {
        int row = wm + mm * 16 + (lane & 15);
        int kb  = lane >> 4;                 // 0 or 1 -> +8 halves
        offA[mm] = (uint32_t)((row * LDH + kb * 8) * 2);
    }
    // B: x4 covers n-blocks nn2*16..+15: (n0-7,k0),(n0-7,k8),(n8-15,k0),(n8-15,k8)
    uint32_t offB[2];
    #pragma unroll
    for (int nn2 = 0; nn2 < 2; nn2++) {
        int n  = wn + nn2 * 16 + (lane & 7) + ((lane >> 4) ? 8 : 0);
        int kb = (lane >> 3) & 1;
        offB[nn2] = (uint32_t)((n * LDH + kb * 8) * 2);
    }

    float acc[4][4][4];
    #pragma unroll
    for (int a = 0; a < 4; a++)
        #pragma unroll
        for (int b2 = 0; b2 < 4; b2++)
            #pragma unroll
            for (int c2 = 0; c2 < 4; c2++) acc[a][b2][c2] = 0.f;

    float rsum = 0.f, rsq = 0.f;
    int srow = tid & 127, skh = (tid >> 7) * 16;

    const int KT = KDIM / BK;
    for (int kt = 0; kt < KT; kt++) {
        int cur = kt & 1;
        if (kt + 1 < KT) load_stage(cur ^ 1, kt + 1);
        asm volatile("cp.async.commit_group;\n");
        asm volatile("cp.async.wait_group 1;\n");
        __syncthreads();

        if (FUSE) {   // per-token LN stats from the fp16 A tile
            const uint4* p = reinterpret_cast<const uint4*>(&sA[cur][srow][skh]);
            #pragma unroll
            for (int h = 0; h < 2; h++) {
                uint4 q = p[h];
                const uint32_t w4[4] = {q.x, q.y, q.z, q.w};
                #pragma unroll
                for (int wq = 0; wq < 4; wq++) {
                    __half2 hv = *reinterpret_cast<const __half2*>(&w4[wq]);
                    float2 f = __half22float2(hv);
                    rsum += f.x + f.y;
                    rsq  += f.x * f.x + f.y * f.y;
                }
            }
        }

        uint32_t aBuf = sA_u + (uint32_t)cur * BUFA;
        uint32_t bBuf = sB_u + (uint32_t)cur * BUFB;

        #pragma unroll
        for (int kk = 0; kk < BK; kk += 16) {
            uint32_t af[4][4], bf[2][4];
            #pragma unroll
            for (int mm = 0; mm < 4; mm++)
                asm volatile(
                    "ldmatrix.sync.aligned.m8n8.x4.shared.b16 {%0,%1,%2,%3}, [%4];\n"
                    : "=r"(af[mm][0]), "=r"(af[mm][1]), "=r"(af[mm][2]), "=r"(af[mm][3])
                    : "r"(aBuf + offA[mm] + kk * 2));
            #pragma unroll
            for (int nn2 = 0; nn2 < 2; nn2++)
                asm volatile(
                    "ldmatrix.sync.aligned.m8n8.x4.shared.b16 {%0,%1,%2,%3}, [%4];\n"
                    : "=r"(bf[nn2][0]), "=r"(bf[nn2][1]), "=r"(bf[nn2][2]), "=r"(bf[nn2][3])
                    : "r"(bBuf + offB[nn2] + kk * 2));

            #pragma unroll
            for (int mm = 0; mm < 4; mm++)
                #pragma unroll
                for (int nn = 0; nn < 4; nn++) {
                    const uint32_t b0 = bf[nn >> 1][(nn & 1) * 2 + 0];
                    const uint32_t b1 = bf[nn >> 1][(nn & 1) * 2 + 1];
                    asm volatile(
                        "mma.sync.aligned.m16n8k16.row.col.f32.f16.f16.f32 "
                        "{%0,%1,%2,%3}, {%4,%5,%6,%7}, {%8,%9}, {%0,%1,%2,%3};\n"
                        : "+f"(acc[mm][nn][0]), "+f"(acc[mm][nn][1]),
                          "+f"(acc[mm][nn][2]), "+f"(acc[mm][nn][3])
                        : "r"(af[mm][0]), "r"(af[mm][1]), "r"(af[mm][2]), "r"(af[mm][3]),
                          "r"(b0), "r"(b1));
                }
        }
        __syncthreads();
    }

    // ---- epilogue ----
    if (FUSE) {
        if (tid < 128) { s_m[tid] = rsum; s_r[tid] = rsq; }
        __syncthreads();
        if (tid >= 128) { s_m[tid - 128] += rsum; s_r[tid - 128] += rsq; }
        __syncthreads();
        if (tid < 128) {
            float mu  = s_m[tid] * (1.0f / (float)KDIM);
            float var = s_r[tid] * (1.0f / (float)KDIM) - mu * mu;
            s_m[tid] = mu;
            s_r[tid] = rsqrtf(var + 1e-5f);
            s_c0[tid] = g_colsum[colB0 + tid];
            s_c1[tid] = g_bsum[colB0 + tid];
        }
        __syncthreads();
    } else {
        if (tid < 128) s_c1[tid] = bias[colB0 + tid];
        __syncthreads();
    }

    int g = lane >> 2, t4 = lane & 3;
    #pragma unroll
    for (int mm = 0; mm < 4; mm++) {
        #pragma unroll
        for (int nn = 0; nn < 4; nn++) {
            #pragma unroll
            for (int rh = 0; rh < 2; rh++) {
                int rl = wm + mm * 16 + g + rh * 8;
                int cl = wn + nn * 8 + 2 * t4;
                float v0 = acc[mm][nn][rh * 2 + 0];
                float v1 = acc[mm][nn][rh * 2 + 1];
                if (FUSE) {
                    float p0 = s_r[rl] * (v0 - s_m[rl] * s_c0[cl])     + s_c1[cl];
                    float p1 = s_r[rl] * (v1 - s_m[rl] * s_c0[cl + 1]) + s_c1[cl + 1];
                    __half2 o = __floats2half2_rn(gelu_t(p0), gelu_t(p1));
                    *reinterpret_cast<__half2*>(
                        CoutH + (size_t)(rowA0 + rl) * C_DIM + colB0 + cl) = o;
                } else {
                    float2 o = make_float2(v0 + s_c1[cl], v1 + s_c1[cl + 1]);
                    *reinterpret_cast<float2*>(
                        CoutF + (size_t)(rowA0 + rl) * C_DIM + colB0 + cl) = o;
                }
            }
        }
    }
}

// ---------------- launch ----------------
extern "C" void kernel_launch(void* const* d_in, const int* in_sizes, int n_in,
                              void* d_out, int out_size) {
    const float* x     = (const float*)d_in[0];
    const float* ln1w  = (const float*)d_in[1];
    const float* ln1b  = (const float*)d_in[2];
    const float* fc1w  = (const float*)d_in[3];
    const float* ln2w  = (const float*)d_in[4];
    const float* ln2b  = (const float*)d_in[5];
    const float* fc2w  = (const float*)d_in[6];
    const float* projw = (const float*)d_in[7];
    const float* projb = (const float*)d_in[8];
    float* out = (float*)d_out;

    prep_fc2 <<<(C_DIM * K2DIM + 255) / 256, 256>>>(fc2w, ln2w);
    prep_proj<<<(C_DIM * C_DIM + 255) / 256, 256>>>(projw);
    prep_sums<<<C_DIM, 128>>>(fc2w, ln2w, ln2b);

    stage1<<<dim3(BATCH, 3), 256>>>(x, ln1w, ln1b, fc1w);

    __half* xfuse_p; cudaGetSymbolAddress((void**)&xfuse_p, g_xfuse);
    __half* y_p;     cudaGetSymbolAddress((void**)&y_p,     g_y);
    __half* fc2_p;   cudaGetSymbolAddress((void**)&fc2_p,   g_fc2p);
    __half* proj_p;  cudaGetSymbolAddress((void**)&proj_p,  g_projp);

    gemm_fp16<K2DIM, true ><<<dim3(C_DIM / BN, TOKENS / BM), 256>>>(
        xfuse_p, fc2_p, nullptr, nullptr, y_p);
    gemm_fp16<C_DIM, false><<<dim3(C_DIM / BN, TOKENS / BM), 256>>>(
        y_p, proj_p, projb, out, nullptr);
}

// round 5
// speedup vs baseline: 1.9488x; 1.0873x over previous
#include <cuda_runtime.h>
#include <cuda_fp16.h>
#include <cstdint>
#include <math.h>

// Problem constants
#define BATCH   512
#define NTOK    64
#define C_DIM   768
#define K2DIM   2304          // 3*C
#define TOKENS  (BATCH * NTOK)   // 32768

// ---------------- device scratch (no allocation allowed) ----------------
__device__ __half g_xfuse[(size_t)TOKENS * K2DIM];   // [token][3C], fp16
__device__ __half g_y[(size_t)TOKENS * C_DIM];       // stage-2 output, fp16
__device__ __half g_fc2p[C_DIM * K2DIM];             // fc2 * ln2_w, fp16
__device__ __half g_projp[C_DIM * C_DIM];            // proj_w, fp16
__device__ float  g_colsum[C_DIM];                   // sum_k ln2_w[k]*fc2[o,k]
__device__ float  g_bsum[C_DIM];                     // sum_k ln2_b[k]*fc2[o,k]

// ---------------- helpers ----------------
__device__ __forceinline__ float tanh_fast(float x) {
    float y;
    asm("tanh.approx.f32 %0, %1;" : "=f"(y) : "f"(x));
    return y;
}
__device__ __forceinline__ float gelu_t(float x) {
    float u = 0.7978845608028654f * (x + 0.044715f * x * x * x);
    return 0.5f * x * (1.0f + tanh_fast(u));
}

// ---------------- K0: weight prep ----------------
__global__ void prep_fc2(const float* __restrict__ fc2, const float* __restrict__ w) {
    int i = blockIdx.x * blockDim.x + threadIdx.x;
    if (i < C_DIM * K2DIM) g_fc2p[i] = __float2half_rn(fc2[i] * w[i % K2DIM]);
}

__global__ void prep_proj(const float* __restrict__ p) {
    int i = blockIdx.x * blockDim.x + threadIdx.x;
    if (i < C_DIM * C_DIM) g_projp[i] = __float2half_rn(p[i]);
}

__global__ void prep_sums(const float* __restrict__ fc2, const float* __restrict__ w,
                          const float* __restrict__ b) {
    int o = blockIdx.x;
    float cs = 0.f, bs = 0.f;
    for (int k = threadIdx.x; k < K2DIM; k += blockDim.x) {
        float f = fc2[o * K2DIM + k];
        cs += f * w[k];
        bs += f * b[k];
    }
    __shared__ float scs[32], sbs[32];
    #pragma unroll
    for (int off = 16; off; off >>= 1) {
        cs += __shfl_down_sync(0xffffffffu, cs, off);
        bs += __shfl_down_sync(0xffffffffu, bs, off);
    }
    int wid = threadIdx.x >> 5, lane = threadIdx.x & 31;
    if (lane == 0) { scs[wid] = cs; sbs[wid] = bs; }
    __syncthreads();
    if (threadIdx.x == 0) {
        float c2 = 0.f, b2 = 0.f;
        int nw = blockDim.x >> 5;
        for (int i = 0; i < nw; i++) { c2 += scs[i]; b2 += sbs[i]; }
        g_colsum[o] = c2; g_bsum[o] = b2;
    }
}

// ---------------- K1: per-(b,c) 8x8 mixing (streaming, low-reg) ----------------
__global__ __launch_bounds__(256, 2) void stage1(
        const float* __restrict__ x,
        const float* __restrict__ ln1w, const float* __restrict__ ln1b,
        const float* __restrict__ fc1w) {
    __shared__ float s_fc1[64], s_w[8], s_b[8];
    int tid = threadIdx.x;
    if (tid < 64) s_fc1[tid] = fc1w[tid];
    if (tid < 8) { s_w[tid] = ln1w[tid]; s_b[tid] = ln1b[tid]; }
    __syncthreads();

    int b = blockIdx.x;
    int c = blockIdx.y * 256 + tid;          // grid.y = 3 -> c in [0,768)
    const float* xb = x + (size_t)b * NTOK * C_DIM;
    __half* rowbase = g_xfuse + (size_t)b * NTOK * K2DIM;

    float M[64];
    #pragma unroll
    for (int n = 0; n < 64; n++) M[n] = xb[n * C_DIM + c];

    // x5 part
    #pragma unroll
    for (int n = 0; n < 64; n++)
        rowbase[(size_t)n * K2DIM + c] = __float2half_rn(M[n]);

    // column LN -> A column j -> xh column j (streamed)
    #pragma unroll
    for (int j = 0; j < 8; j++) {
        float m = 0.f;
        #pragma unroll
        for (int t = 0; t < 8; t++) m += M[t * 8 + j];
        m *= 0.125f;
        float v = 0.f;
        #pragma unroll
        for (int t = 0; t < 8; t++) { float d = M[t * 8 + j] - m; v += d * d; }
        float rs = rsqrtf(v * 0.125f + 1e-5f);
        float ln[8];
        #pragma unroll
        for (int t = 0; t < 8; t++)
            ln[t] = (M[t * 8 + j] - m) * rs * s_w[t] + s_b[t];
        float acol[8];
        #pragma unroll
        for (int io = 0; io < 8; io++) {
            float a = 0.f;
            #pragma unroll
            for (int t = 0; t < 8; t++) a += s_fc1[io * 8 + t] * ln[t];
            acol[io] = gelu_t(a);
        }
        #pragma unroll
        for (int i = 0; i < 8; i++) {
            float xh = 0.f;
            #pragma unroll
            for (int t = 0; t < 8; t++) xh += M[i * 8 + t] * acol[t];
            rowbase[(size_t)(i * 8 + j) * K2DIM + C_DIM + c] = __float2half_rn(xh);
        }
    }
    // row LN -> W row i -> xw row i (streamed)
    #pragma unroll
    for (int i = 0; i < 8; i++) {
        float m = 0.f;
        #pragma unroll
        for (int t = 0; t < 8; t++) m += M[i * 8 + t];
        m *= 0.125f;
        float v = 0.f;
        #pragma unroll
        for (int t = 0; t < 8; t++) { float d = M[i * 8 + t] - m; v += d * d; }
        float rs = rsqrtf(v * 0.125f + 1e-5f);
        float ln[8];
        #pragma unroll
        for (int t = 0; t < 8; t++)
            ln[t] = (M[i * 8 + t] - m) * rs * s_w[t] + s_b[t];
        float wrow[8];
        #pragma unroll
        for (int jo = 0; jo < 8; jo++) {
            float a = 0.f;
            #pragma unroll
            for (int t = 0; t < 8; t++) a += ln[t] * s_fc1[jo * 8 + t];
            wrow[jo] = gelu_t(a);
        }
        #pragma unroll
        for (int j = 0; j < 8; j++) {
            float xw = 0.f;
            #pragma unroll
            for (int t = 0; t < 8; t++) xw += wrow[t] * M[t * 8 + j];
            rowbase[(size_t)(i * 8 + j) * K2DIM + 2 * C_DIM + c] = __float2half_rn(xw);
        }
    }
}

// ---------------- K2/K3: FP16 tensor-core GEMM (m16n8k16 + ldmatrix, 4-stage) ----------------
// C[M,768] = A[M,KDIM] @ B[768,KDIM]^T   (A,B fp16 row-major k-contiguous, fp32 acc)
#define BM 128
#define BN 128
#define BK 32                      // halves per tile row (64B)
#define LDH 40                     // padded smem stride in halves (80B, 16B-aligned)
#define STAGES 4
#define TILE_H (BM * LDH)          // halves per operand stage
#define SMEM_BYTES (STAGES * 2 * TILE_H * 2)   // 81920 B

__device__ __forceinline__ void cp16(uint32_t smem, const void* g) {
    asm volatile("cp.async.cg.shared.global [%0], [%1], 16;\n" :: "r"(smem), "l"(g));
}

template<int KDIM, bool FUSE>
__global__ __launch_bounds__(256, 2) void gemm_fp16(const __half* __restrict__ Ag,
                                                    const __half* __restrict__ Bg,
                                                    const float* __restrict__ bias,
                                                    float* __restrict__ CoutF,
                                                    __half* __restrict__ CoutH) {
    extern __shared__ __half smh[];
    // layout: [STAGES][A:TILE_H][B:TILE_H]
    __shared__ float s_m[BM], s_r[BM], s_c0[BN], s_c1[BN];

    int tid = threadIdx.x;
    int rowA0 = blockIdx.y * BM;     // M tile
    int colB0 = blockIdx.x * BN;     // N tile (x fast -> wave shares A in L2)
    const __half* Abase = Ag + (size_t)rowA0 * KDIM;
    const __half* Bbase = Bg + (size_t)colB0 * KDIM;

    uint32_t smem_u = (uint32_t)__cvta_generic_to_shared(smh);
    const uint32_t STAGE_B = 2 * TILE_H * 2;     // bytes per stage (A+B)

    int lr = tid >> 1;               // 0..127 (tile row)
    int lc = (tid & 1) * 16;         // half-offset 0 or 16
    uint32_t sOffA = (uint32_t)((lr * LDH + lc) * 2);
    uint32_t sOffB = sOffA + TILE_H * 2;

    auto load_stage = [&](int buf, int kt) {
        uint32_t base = smem_u + (uint32_t)buf * STAGE_B;
        const __half* a0 = Abase + (size_t)lr * KDIM + kt * BK + lc;
        cp16(base + sOffA,      a0);
        cp16(base + sOffA + 16, a0 + 8);
        const __half* b0 = Bbase + (size_t)lr * KDIM + kt * BK + lc;
        cp16(base + sOffB,      b0);
        cp16(base + sOffB + 16, b0 + 8);
        asm volatile("cp.async.commit_group;\n");
    };

    const int KT = KDIM / BK;
    #pragma unroll
    for (int p = 0; p < STAGES - 1; p++) load_stage(p, p);

    int wid = tid >> 5, lane = tid & 31;
    int wm = (wid & 1) * 64;         // warp row base
    int wn = (wid >> 1) * 32;        // warp col base

    // ldmatrix per-lane byte offsets within a stage
    uint32_t offA[4];
    #pragma unroll
    for (int mm = 0; mm < 4; mm++) {
        int row = wm + mm * 16 + (lane & 15);
        int kb  = lane >> 4;                 // 0/1 -> +8 halves
        offA[mm] = (uint32_t)((row * LDH + kb * 8) * 2);
    }
    uint32_t offB[2];
    #pragma unroll
    for (int nn2 = 0; nn2 < 2; nn2++) {
        int n  = wn + nn2 * 16 + (lane & 7) + ((lane >> 4) ? 8 : 0);
        int kb = (lane >> 3) & 1;
        offB[nn2] = (uint32_t)((n * LDH + kb * 8) * 2 + TILE_H * 2);
    }

    float acc[4][4][4];
    #pragma unroll
    for (int a = 0; a < 4; a++)
        #pragma unroll
        for (int b2 = 0; b2 < 4; b2++)
            #pragma unroll
            for (int c2 = 0; c2 < 4; c2++) acc[a][b2][c2] = 0.f;

    float rsum = 0.f, rsq = 0.f;
    int srow = tid & 127, skh = (tid >> 7) * 16;
    uint32_t statOff = (uint32_t)((srow * LDH + skh) * 2);

    for (int s = 0; s < KT; s++) {
        asm volatile("cp.async.wait_group %0;\n" :: "n"(STAGES - 2));
        __syncthreads();

        int p = s + STAGES - 1;
        if (p < KT) load_stage(p % STAGES, p);   // issue next loads early

        uint32_t stage = smem_u + (uint32_t)(s % STAGES) * STAGE_B;

        if (FUSE) {   // per-token LN stats from the fp16 A tile
            uint4 q0, q1;
            asm volatile("ld.shared.v4.u32 {%0,%1,%2,%3}, [%4];"
                         : "=r"(q0.x), "=r"(q0.y), "=r"(q0.z), "=r"(q0.w)
                         : "r"(stage + statOff));
            asm volatile("ld.shared.v4.u32 {%0,%1,%2,%3}, [%4];"
                         : "=r"(q1.x), "=r"(q1.y), "=r"(q1.z), "=r"(q1.w)
                         : "r"(stage + statOff + 16));
            const uint32_t wv[8] = {q0.x, q0.y, q0.z, q0.w, q1.x, q1.y, q1.z, q1.w};
            #pragma unroll
            for (int wq = 0; wq < 8; wq++) {
                __half2 hv = *reinterpret_cast<const __half2*>(&wv[wq]);
                float2 f = __half22float2(hv);
                rsum += f.x + f.y;
                rsq  += f.x * f.x + f.y * f.y;
            }
        }

        #pragma unroll
        for (int kk = 0; kk < BK; kk += 16) {
            uint32_t af[4][4], bf[2][4];
            #pragma unroll
            for (int mm = 0; mm < 4; mm++)
                asm volatile(
                    "ldmatrix.sync.aligned.m8n8.x4.shared.b16 {%0,%1,%2,%3}, [%4];\n"
                    : "=r"(af[mm][0]), "=r"(af[mm][1]), "=r"(af[mm][2]), "=r"(af[mm][3])
                    : "r"(stage + offA[mm] + kk * 2));
            #pragma unroll
            for (int nn2 = 0; nn2 < 2; nn2++)
                asm volatile(
                    "ldmatrix.sync.aligned.m8n8.x4.shared.b16 {%0,%1,%2,%3}, [%4];\n"
                    : "=r"(bf[nn2][0]), "=r"(bf[nn2][1]), "=r"(bf[nn2][2]), "=r"(bf[nn2][3])
                    : "r"(stage + offB[nn2] + kk * 2));

            #pragma unroll
            for (int mm = 0; mm < 4; mm++)
                #pragma unroll
                for (int nn = 0; nn < 4; nn++) {
                    const uint32_t b0 = bf[nn >> 1][(nn & 1) * 2 + 0];
                    const uint32_t b1 = bf[nn >> 1][(nn & 1) * 2 + 1];
                    asm volatile(
                        "mma.sync.aligned.m16n8k16.row.col.f32.f16.f16.f32 "
                        "{%0,%1,%2,%3}, {%4,%5,%6,%7}, {%8,%9}, {%0,%1,%2,%3};\n"
                        : "+f"(acc[mm][nn][0]), "+f"(acc[mm][nn][1]),
                          "+f"(acc[mm][nn][2]), "+f"(acc[mm][nn][3])
                        : "r"(af[mm][0]), "r"(af[mm][1]), "r"(af[mm][2]), "r"(af[mm][3]),
                          "r"(b0), "r"(b1));
                }
        }
    }

    // ---- epilogue ----
    __syncthreads();
    if (FUSE) {
        if (tid < 128) { s_m[tid] = rsum; s_r[tid] = rsq; }
        __syncthreads();
        if (tid >= 128) { s_m[tid - 128] += rsum; s_r[tid - 128] += rsq; }
        __syncthreads();
        if (tid < 128) {
            float mu  = s_m[tid] * (1.0f / (float)KDIM);
            float var = s_r[tid] * (1.0f / (float)KDIM) - mu * mu;
            s_m[tid] = mu;
            s_r[tid] = rsqrtf(var + 1e-5f);
            s_c0[tid] = g_colsum[colB0 + tid];
            s_c1[tid] = g_bsum[colB0 + tid];
        }
        __syncthreads();
    } else {
        if (tid < 128) s_c1[tid] = bias[colB0 + tid];
        __syncthreads();
    }

    int g = lane >> 2, t4 = lane & 3;
    #pragma unroll
    for (int mm = 0; mm < 4; mm++) {
        #pragma unroll
        for (int nn = 0; nn < 4; nn++) {
            #pragma unroll
            for (int rh = 0; rh < 2; rh++) {
                int rl = wm + mm * 16 + g + rh * 8;
                int cl = wn + nn * 8 + 2 * t4;
                float v0 = acc[mm][nn][rh * 2 + 0];
                float v1 = acc[mm][nn][rh * 2 + 1];
                if (FUSE) {
                    float p0 = s_r[rl] * (v0 - s_m[rl] * s_c0[cl])     + s_c1[cl];
                    float p1 = s_r[rl] * (v1 - s_m[rl] * s_c0[cl + 1]) + s_c1[cl + 1];
                    __half2 o = __floats2half2_rn(gelu_t(p0), gelu_t(p1));
                    *reinterpret_cast<__half2*>(
                        CoutH + (size_t)(rowA0 + rl) * C_DIM + colB0 + cl) = o;
                } else {
                    float2 o = make_float2(v0 + s_c1[cl], v1 + s_c1[cl + 1]);
                    *reinterpret_cast<float2*>(
                        CoutF + (size_t)(rowA0 + rl) * C_DIM + colB0 + cl) = o;
                }
            }
        }
    }
}

// ---------------- launch ----------------
extern "C" void kernel_launch(void* const* d_in, const int* in_sizes, int n_in,
                              void* d_out, int out_size) {
    const float* x     = (const float*)d_in[0];
    const float* ln1w  = (const float*)d_in[1];
    const float* ln1b  = (const float*)d_in[2];
    const float* fc1w  = (const float*)d_in[3];
    const float* ln2w  = (const float*)d_in[4];
    const float* ln2b  = (const float*)d_in[5];
    const float* fc2w  = (const float*)d_in[6];
    const float* projw = (const float*)d_in[7];
    const float* projb = (const float*)d_in[8];
    float* out = (float*)d_out;

    static int attr_done = 0;
    if (!attr_done) {
        cudaFuncSetAttribute(gemm_fp16<K2DIM, true >,
                             cudaFuncAttributeMaxDynamicSharedMemorySize, SMEM_BYTES);
        cudaFuncSetAttribute(gemm_fp16<C_DIM, false>,
                             cudaFuncAttributeMaxDynamicSharedMemorySize, SMEM_BYTES);
        attr_done = 1;
    }

    prep_fc2 <<<(C_DIM * K2DIM + 255) / 256, 256>>>(fc2w, ln2w);
    prep_proj<<<(C_DIM * C_DIM + 255) / 256, 256>>>(projw);
    prep_sums<<<C_DIM, 128>>>(fc2w, ln2w, ln2b);

    stage1<<<dim3(BATCH, 3), 256>>>(x, ln1w, ln1b, fc1w);

    __half* xfuse_p; cudaGetSymbolAddress((void**)&xfuse_p, g_xfuse);
    __half* y_p;     cudaGetSymbolAddress((void**)&y_p,     g_y);
    __half* fc2_p;   cudaGetSymbolAddress((void**)&fc2_p,   g_fc2p);
    __half* proj_p;  cudaGetSymbolAddress((void**)&proj_p,  g_projp);

    gemm_fp16<K2DIM, true ><<<dim3(C_DIM / BN, TOKENS / BM), 256, SMEM_BYTES>>>(
        xfuse_p, fc2_p, nullptr, nullptr, y_p);
    gemm_fp16<C_DIM, false><<<dim3(C_DIM / BN, TOKENS / BM), 256, SMEM_BYTES>>>(
        y_p, proj_p, projb, out, nullptr);
}